// round 4
// baseline (speedup 1.0000x reference)
#include <cuda_runtime.h>
#include <cstdint>

// Problem constants
#define BATCH 2
#define SEQ   2048
#define DMODEL 2048
#define NHEADS 16
#define HDIM  128
#define MROWS (BATCH*SEQ)          // 4096
#define PAIRS (BATCH*NHEADS)       // 32
#define EXP_SHIFT 20.0f

// ---------------- scratch (static __device__ globals; no allocation) --------
__device__ float g_Xt [MROWS*DMODEL];
__device__ float g_Wqt[DMODEL*DMODEL];
__device__ float g_Wkt[DMODEL*DMODEL];
__device__ float g_Wvt[DMODEL*DMODEL];
__device__ float g_Wot[DMODEL*DMODEL];
__device__ float g_Q  [MROWS*DMODEL];
__device__ float g_K  [MROWS*DMODEL];
__device__ float g_V  [MROWS*DMODEL];
__device__ float g_AO [MROWS*DMODEL];
__device__ float g_S  [(size_t)PAIRS*SEQ*SEQ];     // 512 MB exp-scores scratch

// ---------------- helpers ----------------------------------------------------
__device__ __forceinline__ float to_tf32(float v) {
    uint32_t r;
    asm("cvt.rna.tf32.f32 %0, %1;" : "=r"(r) : "f"(v));
    return __uint_as_float(r);
}

__device__ __forceinline__ void cp_async16(float* smem_dst, const float* gmem_src) {
    uint32_t s = (uint32_t)__cvta_generic_to_shared(smem_dst);
    asm volatile("cp.async.cg.shared.global [%0], [%1], 16;\n" :: "r"(s), "l"(gmem_src));
}
#define CP_COMMIT()  asm volatile("cp.async.commit_group;\n")
#define CP_WAIT(n)   asm volatile("cp.async.wait_group %0;\n" :: "n"(n))

// ---------------- elementwise fp32 -> tf32 (round-to-nearest) ---------------
__global__ void round_tf32_kernel(const float4* __restrict__ in,
                                  float4* __restrict__ out, int n4) {
    int i = blockIdx.x * blockDim.x + threadIdx.x;
    int stride = gridDim.x * blockDim.x;
    for (; i < n4; i += stride) {
        float4 v = in[i];
        v.x = to_tf32(v.x); v.y = to_tf32(v.y);
        v.z = to_tf32(v.z); v.w = to_tf32(v.w);
        out[i] = v;
    }
}

// ---------------- per-head RMSNorm (+ extra scale + tf32 round), in place ----
__global__ void __launch_bounds__(256)
rmsnorm_kernel(float* __restrict__ q, const float* __restrict__ gamma,
               float post_scale, int total_warps) {
    int gw   = (blockIdx.x * 256 + threadIdx.x) >> 5;
    int lane = threadIdx.x & 31;
    if (gw >= total_warps) return;
    float* p = q + (size_t)gw * HDIM;
    float v0 = p[lane], v1 = p[lane+32], v2 = p[lane+64], v3 = p[lane+96];
    float ss = v0*v0 + v1*v1 + v2*v2 + v3*v3;
    #pragma unroll
    for (int o = 16; o; o >>= 1) ss += __shfl_xor_sync(0xffffffffu, ss, o);
    float r = rsqrtf(ss * (1.0f/128.0f) + 1e-6f) * post_scale;
    p[lane]    = to_tf32(v0 * r * gamma[lane]);
    p[lane+32] = to_tf32(v1 * r * gamma[lane+32]);
    p[lane+64] = to_tf32(v2 * r * gamma[lane+64]);
    p[lane+96] = to_tf32(v3 * r * gamma[lane+96]);
}

// ---------------- generic TF32 tensor-core GEMM, 2-stage cp.async pipeline ---
// C[M,N] = A[M,K] * op(B). NN: B row-major [K,N]; NT: B row-major [N,K] (C=A*B^T)
// EPI: 0 = plain fp32 store; 1 = tf32-rounded store;
//      2 = tf32(exp(acc - EXP_SHIFT));
//      3 = tf32(acc / rowsum(A)) with rowsum computed in-loop from smem
//          (valid ONLY when this block's A tiles span the full K extent of
//           each row, i.e. gridDim.x == 1 covers all of N and A rows are
//           disjoint per block -- true for the PV GEMM here).
#define AS_STAGE 4608          // 128*36
#define BS_STAGE_NT 4608       // 128*36
#define BS_STAGE_NN 4352       // 32*136

template<bool NT, int EPI>
__global__ void __launch_bounds__(256)
gemm_tf32_kernel(const float* __restrict__ A, const float* __restrict__ B,
                 float* __restrict__ C,
                 int K, int lda, int ldb, int ldc,
                 int Z2,
                 long long sA1, long long sA2,
                 long long sB1, long long sB2,
                 long long sC1, long long sC2) {
    const int z  = blockIdx.z;
    int z1 = z / Z2, z2 = z % Z2;
    A += z1 * sA1 + z2 * sA2;
    B += z1 * sB1 + z2 * sB2;
    C += z1 * sC1 + z2 * sC2;

    extern __shared__ float smem[];
    float* As = smem;                 // [2][128][36]
    float* Bs = smem + 2 * AS_STAGE;  // NT: [2][128][36]; NN: [2][32][136]

    const int tid  = threadIdx.x;
    const int lane = tid & 31;
    const int warp = tid >> 5;
    const int wr = warp >> 2;      // 0..1 -> warp row (64)
    const int wc = warp & 3;       // 0..3 -> warp col (32)
    const int bm = blockIdx.y * 128;
    const int bn = blockIdx.x * 128;
    const int g  = lane >> 2;      // groupID 0..7
    const int tg = lane & 3;       // thread-in-group 0..3

    auto load_tile = [&](int kt, int s) {
        const int k0 = kt * 32;
        #pragma unroll
        for (int r = 0; r < 4; r++) {
            int idx = tid + r * 256;
            int row = idx >> 3;          // 8 float4 per row
            int c4  = idx & 7;
            cp_async16(&As[s * AS_STAGE + row * 36 + c4 * 4],
                       A + (long long)(bm + row) * lda + k0 + c4 * 4);
        }
        if (NT) {
            #pragma unroll
            for (int r = 0; r < 4; r++) {
                int idx = tid + r * 256;
                int row = idx >> 3;      // n-row, 8 float4 per row
                int c4  = idx & 7;
                cp_async16(&Bs[s * BS_STAGE_NT + row * 36 + c4 * 4],
                           B + (long long)(bn + row) * ldb + k0 + c4 * 4);
            }
        } else {
            #pragma unroll
            for (int r = 0; r < 4; r++) {
                int idx = tid + r * 256;
                int row = idx >> 5;      // k-row, 32 float4 per row
                int c4  = idx & 31;
                cp_async16(&Bs[s * BS_STAGE_NN + row * 136 + c4 * 4],
                           B + (long long)(k0 + row) * ldb + bn + c4 * 4);
            }
        }
    };

    float acc[4][4][4];
    #pragma unroll
    for (int i = 0; i < 4; i++)
        #pragma unroll
        for (int j = 0; j < 4; j++)
            #pragma unroll
            for (int c = 0; c < 4; c++) acc[i][j][c] = 0.0f;

    float rs_total = 0.0f;             // EPI==3: partial row sum of A

    const int KT = K >> 5;             // k-tiles of 32
    load_tile(0, 0);
    CP_COMMIT();

    for (int kt = 0; kt < KT; kt++) {
        const int s = kt & 1;
        if (kt + 1 < KT) {
            load_tile(kt + 1, s ^ 1);
            CP_COMMIT();
            CP_WAIT(1);                // stage s resident
        } else {
            CP_WAIT(0);
        }
        __syncthreads();

        const float* Asb = &As[s * AS_STAGE];
        const float* Bsb = NT ? &Bs[s * BS_STAGE_NT] : &Bs[s * BS_STAGE_NN];

        if (EPI == 3) {
            // 2 threads per row; thread sums 16 of the 32 k-columns.
            // Fixed order -> deterministic.
            const float* Ap = Asb + (tid >> 1) * 36 + (tid & 1) * 16;
            #pragma unroll
            for (int c = 0; c < 16; c += 4) {
                float4 v = *(const float4*)(Ap + c);
                rs_total += (v.x + v.y) + (v.z + v.w);
            }
        }

        #pragma unroll
        for (int ks = 0; ks < 4; ks++) {
            const int kk = ks * 8;
            uint32_t af[4][4];
            #pragma unroll
            for (int i = 0; i < 4; i++) {
                int r0 = wr * 64 + i * 16 + g;
                af[i][0] = __float_as_uint(Asb[(r0    ) * 36 + kk + tg    ]);
                af[i][1] = __float_as_uint(Asb[(r0 + 8) * 36 + kk + tg    ]);
                af[i][2] = __float_as_uint(Asb[(r0    ) * 36 + kk + tg + 4]);
                af[i][3] = __float_as_uint(Asb[(r0 + 8) * 36 + kk + tg + 4]);
            }
            uint32_t bf[4][2];
            #pragma unroll
            for (int j = 0; j < 4; j++) {
                int n = wc * 32 + j * 8 + g;
                if (NT) {
                    bf[j][0] = __float_as_uint(Bsb[n * 36 + kk + tg    ]);
                    bf[j][1] = __float_as_uint(Bsb[n * 36 + kk + tg + 4]);
                } else {
                    bf[j][0] = __float_as_uint(Bsb[(kk + tg    ) * 136 + n]);
                    bf[j][1] = __float_as_uint(Bsb[(kk + tg + 4) * 136 + n]);
                }
            }
            #pragma unroll
            for (int i = 0; i < 4; i++)
                #pragma unroll
                for (int j = 0; j < 4; j++) {
                    asm volatile(
                        "mma.sync.aligned.m16n8k8.row.col.f32.tf32.tf32.f32 "
                        "{%0,%1,%2,%3}, {%4,%5,%6,%7}, {%8,%9}, {%0,%1,%2,%3};\n"
                        : "+f"(acc[i][j][0]), "+f"(acc[i][j][1]),
                          "+f"(acc[i][j][2]), "+f"(acc[i][j][3])
                        : "r"(af[i][0]), "r"(af[i][1]), "r"(af[i][2]), "r"(af[i][3]),
                          "r"(bf[j][0]), "r"(bf[j][1]));
                }
        }
        __syncthreads();     // stage s fully consumed before it is refilled
    }

    // EPI==3: combine the two half-row partials and publish row sums in smem
    float* rowsum = smem;    // reuse As stage 0 (mainloop finished)
    if (EPI == 3) {
        rs_total += __shfl_xor_sync(0xffffffffu, rs_total, 1);
        if ((tid & 1) == 0) rowsum[tid >> 1] = rs_total;
        __syncthreads();
    }

    // -- epilogue: m16n8 C fragment layout, with fused postprocessing
    #pragma unroll
    for (int i = 0; i < 4; i++) {
        int rl = wr * 64 + i * 16 + g;          // local row in [0,128)
        long long r0 = bm + rl;
        float invA = 1.0f, invB = 1.0f;
        if (EPI == 3) {
            invA = 1.0f / rowsum[rl];
            invB = 1.0f / rowsum[rl + 8];
        }
        #pragma unroll
        for (int j = 0; j < 4; j++) {
            int c0 = bn + wc * 32 + j * 8 + tg * 2;
            float o0 = acc[i][j][0], o1 = acc[i][j][1];
            float o2 = acc[i][j][2], o3 = acc[i][j][3];
            if (EPI == 1) {
                o0 = to_tf32(o0); o1 = to_tf32(o1);
                o2 = to_tf32(o2); o3 = to_tf32(o3);
            } else if (EPI == 2) {
                o0 = to_tf32(__expf(o0 - EXP_SHIFT));
                o1 = to_tf32(__expf(o1 - EXP_SHIFT));
                o2 = to_tf32(__expf(o2 - EXP_SHIFT));
                o3 = to_tf32(__expf(o3 - EXP_SHIFT));
            } else if (EPI == 3) {
                o0 = to_tf32(o0 * invA); o1 = to_tf32(o1 * invA);
                o2 = to_tf32(o2 * invB); o3 = to_tf32(o3 * invB);
            }
            C[r0 * ldc + c0]           = o0;
            C[r0 * ldc + c0 + 1]       = o1;
            C[(r0 + 8) * ldc + c0]     = o2;
            C[(r0 + 8) * ldc + c0 + 1] = o3;
        }
    }
}

#define SMEM_NT ((2*AS_STAGE + 2*BS_STAGE_NT) * 4)   // 73728 B
#define SMEM_NN ((2*AS_STAGE + 2*BS_STAGE_NN) * 4)   // 71680 B

// ---------------- launcher ----------------------------------------------------
extern "C" void kernel_launch(void* const* d_in, const int* in_sizes, int n_in,
                              void* d_out, int out_size) {
    (void)in_sizes; (void)n_in; (void)out_size;
    const float* x  = (const float*)d_in[0];
    const float* Wq = (const float*)d_in[1];
    const float* Wk = (const float*)d_in[2];
    const float* Wv = (const float*)d_in[3];
    const float* Wo = (const float*)d_in[4];
    const float* qg = (const float*)d_in[5];
    const float* kg = (const float*)d_in[6];
    float* out = (float*)d_out;

    float *Xt, *Wqt, *Wkt, *Wvt, *Wot, *Q, *Kb, *V, *AO, *S;
    cudaGetSymbolAddress((void**)&Xt,  g_Xt);
    cudaGetSymbolAddress((void**)&Wqt, g_Wqt);
    cudaGetSymbolAddress((void**)&Wkt, g_Wkt);
    cudaGetSymbolAddress((void**)&Wvt, g_Wvt);
    cudaGetSymbolAddress((void**)&Wot, g_Wot);
    cudaGetSymbolAddress((void**)&Q,   g_Q);
    cudaGetSymbolAddress((void**)&Kb,  g_K);
    cudaGetSymbolAddress((void**)&V,   g_V);
    cudaGetSymbolAddress((void**)&AO,  g_AO);
    cudaGetSymbolAddress((void**)&S,   g_S);

    cudaFuncSetAttribute(gemm_tf32_kernel<false,0>,
                         cudaFuncAttributeMaxDynamicSharedMemorySize, SMEM_NN);
    cudaFuncSetAttribute(gemm_tf32_kernel<false,1>,
                         cudaFuncAttributeMaxDynamicSharedMemorySize, SMEM_NN);
    cudaFuncSetAttribute(gemm_tf32_kernel<false,3>,
                         cudaFuncAttributeMaxDynamicSharedMemorySize, SMEM_NN);
    cudaFuncSetAttribute(gemm_tf32_kernel<true,2>,
                         cudaFuncAttributeMaxDynamicSharedMemorySize, SMEM_NT);

    const int M = MROWS, D = DMODEL;
    const long long PS = (long long)SEQ * SEQ;   // per-(b,h) scores stride

    // 1) round all GEMM inputs to tf32 (rna) for accuracy
    round_tf32_kernel<<<2048, 256>>>((const float4*)x,  (float4*)Xt,  M*D/4);
    round_tf32_kernel<<<2048, 256>>>((const float4*)Wq, (float4*)Wqt, D*D/4);
    round_tf32_kernel<<<2048, 256>>>((const float4*)Wk, (float4*)Wkt, D*D/4);
    round_tf32_kernel<<<2048, 256>>>((const float4*)Wv, (float4*)Wvt, D*D/4);
    round_tf32_kernel<<<2048, 256>>>((const float4*)Wo, (float4*)Wot, D*D/4);

    // 2) QKV projections: [4096,2048] x [2048,2048]; V output tf32-rounded
    dim3 gProj(D/128, M/128, 1);
    gemm_tf32_kernel<false,0><<<gProj, 256, SMEM_NN>>>(Xt, Wqt, Q,  D, D, D, D, 1, 0,0,0,0,0,0);
    gemm_tf32_kernel<false,0><<<gProj, 256, SMEM_NN>>>(Xt, Wkt, Kb, D, D, D, D, 1, 0,0,0,0,0,0);
    gemm_tf32_kernel<false,1><<<gProj, 256, SMEM_NN>>>(Xt, Wvt, V,  D, D, D, D, 1, 0,0,0,0,0,0);

    // 3) per-head RMSNorm on Q (folds in 1/sqrt(HDIM)) and K, tf32-rounded
    const float att_scale = 0.08838834764831845f;   // 1/sqrt(128)
    rmsnorm_kernel<<<M*NHEADS/8, 256>>>(Q,  qg, att_scale, M*NHEADS);
    rmsnorm_kernel<<<M*NHEADS/8, 256>>>(Kb, kg, 1.0f,      M*NHEADS);

    // 4) exp-scores: per (b,h)  E_bh = exp(Q_bh K_bh^T - SHIFT), tf32-rounded
    dim3 gScores(SEQ/128, SEQ/128, PAIRS);
    gemm_tf32_kernel<true,2><<<gScores, 256, SMEM_NT>>>(
        Q, Kb, S, HDIM, D, D, SEQ,
        NHEADS,
        (long long)SEQ*D, HDIM,
        (long long)SEQ*D, HDIM,
        NHEADS*PS,        PS);

    // 5) PV with fused in-loop rowsum + normalization:
    //    AO_bh = (E_bh V_bh) / rowsum(E_bh)   [gridDim.x == 1 -> full rows]
    dim3 gPV(HDIM/128, SEQ/128, PAIRS);
    gemm_tf32_kernel<false,3><<<gPV, 256, SMEM_NN>>>(
        S, V, AO, SEQ, SEQ, D, D,
        NHEADS,
        NHEADS*PS,        PS,
        (long long)SEQ*D, HDIM,
        (long long)SEQ*D, HDIM);

    // 6) output projection: out = AO x Wo
    gemm_tf32_kernel<false,0><<<gProj, 256, SMEM_NN>>>(AO, Wot, out, D, D, D, D, 1, 0,0,0,0,0,0);
}